// round 15
// baseline (speedup 1.0000x reference)
#include <cuda_runtime.h>

// LengthRegulator: B=32, T=1024, C=384, M=4096. Durations int32; totals appended
// to out as float32 values (confirmed R4/R5).
//
// R15 = R14 engine, persistent-CTA gather: 888 blocks (one wave), grid-stride
// over 8192 tiles of 16 frames. Removes wave transitions + per-CTA churn.

#define BB 32
#define TT 1024
#define CC 384
#define MM 4096
#define C4 (CC / 4)                              // 96 float4 per row
#define MAIN_ELEMS ((long long)BB * MM * CC)     // 50,331,648
#define SEG 8                                    // prep blocks per batch
#define FSEG (MM / SEG)                          // 512 frames per prep block
#define FPB 16                                   // frames per gather tile
#define GT 256                                   // gather threads per block
#define TPB (MM / FPB)                           // 256 tiles per batch
#define NTILES (BB * TPB)                        // 8192
#define PERSIST 888                              // 148 SMs * 6 resident CTAs

__device__ int g_tok[BB * MM];     // token index per frame, -1 => zero-fill

// ---------------------------------------------------------------------------
// Prep: grid (SEG, BB) = 256 CTAs, 256 threads. int4 scan (4 durations/thread),
// then each thread resolves 2 frames of its segment. (R14, proven)
// ---------------------------------------------------------------------------
__global__ __launch_bounds__(256) void lr_prep_kernel(
        const int4* __restrict__ dur4,
        float* __restrict__ out_base) {
    __shared__ int cs[TT];
    __shared__ int wsum[8];

    const int b   = blockIdx.y;
    const int seg = blockIdx.x;
    const int tid = threadIdx.x;                 // 0..255
    const int lane = tid & 31;
    const int w    = tid >> 5;                   // warp 0..7

    const int4 d = dur4[b * (TT / 4) + tid];     // 4 durations per thread
    int e = d.x + d.y + d.z + d.w;
    #pragma unroll
    for (int off = 1; off < 32; off <<= 1) {
        int n = __shfl_up_sync(0xffffffffu, e, off);
        if (lane >= off) e += n;
    }
    if (lane == 31) wsum[w] = e;
    __syncthreads();
    if (tid < 32) {
        int s = (tid < 8) ? wsum[tid] : 0;
        #pragma unroll
        for (int off = 1; off < 8; off <<= 1) {
            int n = __shfl_up_sync(0xffffffffu, s, off);
            if (lane >= off) s += n;
        }
        if (tid < 8) wsum[tid] = s;
    }
    __syncthreads();
    const int base = (w > 0) ? wsum[w - 1] : 0;
    const int end = base + e;                    // inclusive through 4t+3
    cs[4 * tid + 3] = end;
    cs[4 * tid + 2] = end - d.w;
    cs[4 * tid + 1] = end - d.w - d.z;
    cs[4 * tid + 0] = end - d.w - d.z - d.y;
    __syncthreads();

    const int total = cs[TT - 1];
    if (seg == 0 && tid == 0)
        out_base[MAIN_ELEMS + b] = (float)total; // total as float32 value

    #pragma unroll
    for (int k = 0; k < 2; ++k) {
        const int f = seg * FSEG + k * 256 + tid;
        int pos = 0;                              // upper_bound, bit construction
        #pragma unroll
        for (int step = TT / 2; step > 0; step >>= 1) {
            int cand = pos + step;               // cand-1 <= 1022
            if (cs[cand - 1] <= f) pos = cand;
        }
        g_tok[b * MM + f] = (f < total) ? pos : -1;
    }
}

// ---------------------------------------------------------------------------
// Persistent gather: 888 blocks, 256 threads, grid-stride over 8192 tiles.
// Per tile: 16 frames; toks in smem; 6 independent float4 streams per thread.
// ---------------------------------------------------------------------------
__global__ __launch_bounds__(GT) void lr_gather_kernel(
        const float4* __restrict__ x4,
        float4* __restrict__ out4) {
    __shared__ int stok[FPB];
    const int tid = threadIdx.x;

    for (int tile = blockIdx.x; tile < NTILES; tile += PERSIST) {
        const int b  = tile >> 8;                // / TPB
        const int f0 = (tile & (TPB - 1)) << 4;  // * FPB

        if (tid < FPB)
            stok[tid] = g_tok[b * MM + f0 + tid];
        __syncthreads();

        const int obase = (b * MM + f0) * C4;    // < 12.6M, fits int
        const int xbase = b * TT * C4;

        float4 val[6];
        #pragma unroll
        for (int k = 0; k < 6; ++k) {
            const int e  = k * GT + tid;         // 0..1535
            const int fl = e / C4;               // local frame 0..15
            const int c  = e - fl * C4;
            const int tok = stok[fl];
            val[k] = make_float4(0.f, 0.f, 0.f, 0.f);
            if (tok >= 0)
                val[k] = __ldg(&x4[xbase + tok * C4 + c]);
        }
        #pragma unroll
        for (int k = 0; k < 6; ++k)
            __stcs(&out4[obase + k * GT + tid], val[k]);

        __syncthreads();                         // protect stok reuse
    }
}

// ---------------------------------------------------------------------------

extern "C" void kernel_launch(void* const* d_in, const int* in_sizes, int n_in,
                              void* d_out, int out_size) {
    const float4* x4 = (const float4*)d_in[0];
    const int4* dur4 = (const int4*)d_in[1];
    float* out = (float*)d_out;

    dim3 gprep(SEG, BB);                         // (8, 32) = 256 CTAs
    lr_prep_kernel<<<gprep, 256>>>(dur4, out);

    lr_gather_kernel<<<PERSIST, GT>>>(x4, (float4*)d_out);
}

// round 16
// speedup vs baseline: 1.0043x; 1.0043x over previous
#include <cuda_runtime.h>

// LengthRegulator: B=32, T=1024, C=384, M=4096. Durations int32; totals appended
// to out as float32 values (confirmed R4/R5).
//
// R16 = champion config (R14 prep + R12 frame-blocked gather), single change:
// plain stores instead of __stcs. A/B: does eager streaming write-drain cause
// the 38.3us / 61%-DRAM plateau?

#define BB 32
#define TT 1024
#define CC 384
#define MM 4096
#define C4 (CC / 4)                              // 96 float4 per row
#define MAIN_ELEMS ((long long)BB * MM * CC)     // 50,331,648
#define SEG 8                                    // prep blocks per batch
#define FSEG (MM / SEG)                          // 512 frames per prep block
#define FPB 16                                   // frames per gather block
#define GT 256                                   // gather threads per block

__device__ int g_tok[BB * MM];     // token index per frame, -1 => zero-fill

// ---------------------------------------------------------------------------
// Prep: grid (SEG, BB) = 256 CTAs, 256 threads. int4 scan (4 durations/thread),
// then each thread resolves 2 frames of its segment. (R14, proven)
// ---------------------------------------------------------------------------
__global__ __launch_bounds__(256) void lr_prep_kernel(
        const int4* __restrict__ dur4,
        float* __restrict__ out_base) {
    __shared__ int cs[TT];
    __shared__ int wsum[8];

    const int b   = blockIdx.y;
    const int seg = blockIdx.x;
    const int tid = threadIdx.x;                 // 0..255
    const int lane = tid & 31;
    const int w    = tid >> 5;                   // warp 0..7

    const int4 d = dur4[b * (TT / 4) + tid];     // 4 durations per thread
    int e = d.x + d.y + d.z + d.w;
    #pragma unroll
    for (int off = 1; off < 32; off <<= 1) {
        int n = __shfl_up_sync(0xffffffffu, e, off);
        if (lane >= off) e += n;
    }
    if (lane == 31) wsum[w] = e;
    __syncthreads();
    if (tid < 32) {
        int s = (tid < 8) ? wsum[tid] : 0;
        #pragma unroll
        for (int off = 1; off < 8; off <<= 1) {
            int n = __shfl_up_sync(0xffffffffu, s, off);
            if (lane >= off) s += n;
        }
        if (tid < 8) wsum[tid] = s;
    }
    __syncthreads();
    const int base = (w > 0) ? wsum[w - 1] : 0;
    const int end = base + e;                    // inclusive through 4t+3
    cs[4 * tid + 3] = end;
    cs[4 * tid + 2] = end - d.w;
    cs[4 * tid + 1] = end - d.w - d.z;
    cs[4 * tid + 0] = end - d.w - d.z - d.y;
    __syncthreads();

    const int total = cs[TT - 1];
    if (seg == 0 && tid == 0)
        out_base[MAIN_ELEMS + b] = (float)total; // total as float32 value

    #pragma unroll
    for (int k = 0; k < 2; ++k) {
        const int f = seg * FSEG + k * 256 + tid;
        int pos = 0;                              // upper_bound, bit construction
        #pragma unroll
        for (int step = TT / 2; step > 0; step >>= 1) {
            int cand = pos + step;               // cand-1 <= 1022
            if (cs[cand - 1] <= f) pos = cand;
        }
        g_tok[b * MM + f] = (f < total) ? pos : -1;
    }
}

// ---------------------------------------------------------------------------
// Gather: grid (MM/FPB, BB) = (256, 32) = 8192 CTAs, 256 threads.
// 16 frames/block; toks in smem; 6 independent float4 streams per thread.
// PLAIN stores (write-allocate): stores retire at L2 speed; DRAM drain
// overlaps kernel tail instead of gating each store.
// ---------------------------------------------------------------------------
__global__ __launch_bounds__(GT) void lr_gather_kernel(
        const float4* __restrict__ x4,
        float4* __restrict__ out4) {
    __shared__ int stok[FPB];
    const int b  = blockIdx.y;
    const int f0 = blockIdx.x * FPB;
    const int tid = threadIdx.x;

    if (tid < FPB)
        stok[tid] = g_tok[b * MM + f0 + tid];
    __syncthreads();

    const int obase = (b * MM + f0) * C4;        // < 12.6M, fits int
    const int xbase = b * TT * C4;

    float4 val[6];
    #pragma unroll
    for (int k = 0; k < 6; ++k) {
        const int e  = k * GT + tid;             // 0..1535
        const int fl = e / C4;                   // local frame 0..15
        const int c  = e - fl * C4;
        const int tok = stok[fl];
        val[k] = make_float4(0.f, 0.f, 0.f, 0.f);
        if (tok >= 0)
            val[k] = __ldg(&x4[xbase + tok * C4 + c]);
    }
    #pragma unroll
    for (int k = 0; k < 6; ++k)
        out4[obase + k * GT + tid] = val[k];     // plain store (A/B vs __stcs)
}

// ---------------------------------------------------------------------------

extern "C" void kernel_launch(void* const* d_in, const int* in_sizes, int n_in,
                              void* d_out, int out_size) {
    const float4* x4 = (const float4*)d_in[0];
    const int4* dur4 = (const int4*)d_in[1];
    float* out = (float*)d_out;

    dim3 gprep(SEG, BB);                         // (8, 32) = 256 CTAs
    lr_prep_kernel<<<gprep, 256>>>(dur4, out);

    dim3 gg(MM / FPB, BB);                       // (256, 32) = 8192 CTAs
    lr_gather_kernel<<<gg, GT>>>(x4, (float4*)d_out);
}

// round 17
// speedup vs baseline: 1.0918x; 1.0872x over previous
#include <cuda_runtime.h>

// LengthRegulator: B=32, T=1024, C=384, M=4096. Durations int32; totals appended
// to out as float32 values (confirmed R4/R5).
//
// R17: ONE kernel, big blocks. grid (64, 32) = 2048 CTAs x 1024 thr; each block
// redundantly scans its batch's 1024 durations (1 elem/thread, shfl),
// resolves its 64 frames (64-thread search), streams 64x96 float4 with __stcs.
// Redundant-scan cost scales with block COUNT (R9 lesson): 2048 blocks => ~2us.

#define BB 32
#define TT 1024
#define CC 384
#define MM 4096
#define C4 (CC / 4)                              // 96 float4 per row
#define MAIN_ELEMS ((long long)BB * MM * CC)     // 50,331,648
#define FPB 64                                   // frames per block
#define NTHR 1024                                // threads per block
#define EPB (FPB * C4)                           // 6144 float4 per block

__global__ __launch_bounds__(NTHR, 2) void lr_fused_kernel(
        const int* __restrict__ dur,
        const float4* __restrict__ x4,
        float4* __restrict__ out4,
        float* __restrict__ out_base) {
    __shared__ int cs[TT];
    __shared__ int wsum[32];
    __shared__ int stok[FPB];

    const int b   = blockIdx.y;
    const int tid = threadIdx.x;                 // 0..1023
    const int lane = tid & 31;
    const int w    = tid >> 5;                   // warp 0..31

    // ---- scan: 1 duration per thread (R5 prep, proven correct) ----
    int v = dur[b * TT + tid];
    #pragma unroll
    for (int off = 1; off < 32; off <<= 1) {
        int n = __shfl_up_sync(0xffffffffu, v, off);
        if (lane >= off) v += n;
    }
    if (lane == 31) wsum[w] = v;
    __syncthreads();
    if (tid < 32) {
        int s = wsum[lane];
        #pragma unroll
        for (int off = 1; off < 32; off <<= 1) {
            int n = __shfl_up_sync(0xffffffffu, s, off);
            if (lane >= off) s += n;
        }
        wsum[lane] = s;
    }
    __syncthreads();
    cs[tid] = v + ((w > 0) ? wsum[w - 1] : 0);   // inclusive cumsum
    __syncthreads();

    const int total = cs[TT - 1];
    const int f0 = blockIdx.x * FPB;

    if (blockIdx.x == 0 && tid == 0)
        out_base[MAIN_ELEMS + b] = (float)total; // total as float32 value

    // ---- tok for this block's 64 frames ----
    if (tid < FPB) {
        const int f = f0 + tid;
        int pos = 0;                              // upper_bound, bit construction
        #pragma unroll
        for (int step = TT / 2; step > 0; step >>= 1) {
            int cand = pos + step;               // cand-1 <= 1022
            if (cs[cand - 1] <= f) pos = cand;
        }
        stok[tid] = (f < total) ? pos : -1;
    }
    __syncthreads();

    // ---- stream 64 frames: 6 independent float4 per thread ----
    const int obase = (b * MM + f0) * C4;        // < 12.6M, fits int
    const int xbase = b * TT * C4;

    float4 val[6];
    #pragma unroll
    for (int k = 0; k < 6; ++k) {
        const int e  = k * NTHR + tid;           // 0..6143
        const int fl = e / C4;                   // local frame 0..63
        const int c  = e - fl * C4;
        const int tok = stok[fl];
        val[k] = make_float4(0.f, 0.f, 0.f, 0.f);
        if (tok >= 0)
            val[k] = __ldg(&x4[xbase + tok * C4 + c]);
    }
    #pragma unroll
    for (int k = 0; k < 6; ++k)
        __stcs(&out4[obase + k * NTHR + tid], val[k]);
}

// ---------------------------------------------------------------------------

extern "C" void kernel_launch(void* const* d_in, const int* in_sizes, int n_in,
                              void* d_out, int out_size) {
    const float4* x4 = (const float4*)d_in[0];
    const int* dur = (const int*)d_in[1];
    float* out = (float*)d_out;

    dim3 grid(MM / FPB, BB);                     // (64, 32) = 2048 CTAs
    lr_fused_kernel<<<grid, NTHR>>>(dur, x4, (float4*)d_out, out);
}